// round 8
// baseline (speedup 1.0000x reference)
#include <cuda_runtime.h>
#include <cuda_fp16.h>
#include <cstdint>

#define MM 16
#define KK 8192
#define NN 8192
#define GROUPK 128
#define SPLITK 16
#define KC     512             // k per block (= KPER); one staging phase
#define NTILE  128             // columns per block (4 warps x 32 cols)
#define WARPS  4
#define NTHREADS (WARPS * 32)
#define NCB    (NN / NTILE)    // 64 column-blocks
#define ROUNDS (KC / 32)       // 16 rounds of 32-k
#define R4STRIDE  (NN)         // int4 units between rounds (4 rows * NN ints / 4)
#define SCSTRIDE  (NN / 4)     // float4 units per scale-group row

// fp32 partial sums, one slab per K-split (each element written exactly once)
__device__ float g_scratch[SPLITK * MM * NN];   // 8 MB

// (v & 0x000F000F) | 0x64006400 -> half2 (1024+nib_lo, 1024+nib_hi); -1032 exactly -> (nib-8)
__device__ __forceinline__ uint32_t dq4(uint32_t v, half2 c1032) {
    uint32_t h;
    asm("lop3.b32 %0, %1, %2, %3, 0xEA;"
        : "=r"(h) : "r"(v), "r"(0x000F000Fu), "r"(0x64006400u));
    half2 hh = __hsub2(*reinterpret_cast<half2*>(&h), c1032);
    return *reinterpret_cast<uint32_t*>(&hh);
}

__device__ __forceinline__ uint32_t mulsc(uint32_t w, half2 s) {
    half2 r = __hmul2(*reinterpret_cast<half2*>(&w), s);   // fp16 RN: matches reference w
    return *reinterpret_cast<uint32_t*>(&r);
}

__device__ __forceinline__ uint32_t packh2(float a, float b) {
    half2 h = __floats2half2_rn(a, b);
    return *reinterpret_cast<uint32_t*>(&h);
}

__device__ __forceinline__ void mma16816(float* c,
                                         uint32_t a0, uint32_t a1, uint32_t a2, uint32_t a3,
                                         uint32_t b0, uint32_t b1) {
    asm volatile(
        "mma.sync.aligned.m16n8k16.row.col.f32.f16.f16.f32 "
        "{%0,%1,%2,%3}, {%4,%5,%6,%7}, {%8,%9}, {%0,%1,%2,%3};\n"
        : "+f"(c[0]), "+f"(c[1]), "+f"(c[2]), "+f"(c[3])
        : "r"(a0), "r"(a1), "r"(a2), "r"(a3), "r"(b0), "r"(b1));
}

// One int32 of qweight (column c, packed row pr) feeds 4 B-regs (nibble pairs
// (0,4),(1,5),(2,6),(3,7)) of column c; lane (g8,i4) loads int4 = columns
// colbase+4*g8+{0..3} of packed row 4r+i4 -> coalesced 128B per row. MMA group j
// uses column set {colbase+4n+j : n=0..7} (a column permutation we undo in the
// epilogue indexing). A fragments are staged once in smem, permuted to match.
__device__ __forceinline__ void procj(float* acc, uint32_t wj, half2 s,
                                      const uint4& va, const uint4& vb, half2 c1032) {
    uint32_t b00 = mulsc(dq4(wj,       c1032), s);
    uint32_t b01 = mulsc(dq4(wj >> 4,  c1032), s);
    uint32_t b02 = mulsc(dq4(wj >> 8,  c1032), s);
    uint32_t b03 = mulsc(dq4(wj >> 12, c1032), s);
    mma16816(acc, va.x, va.y, va.z, va.w, b00, b01);
    mma16816(acc, vb.x, vb.y, vb.z, vb.w, b02, b03);
}

__global__ void __launch_bounds__(NTHREADS, 7)
qlinear_gemm(const float* __restrict__ x, const int* __restrict__ qweight,
             const float* __restrict__ scales)
{
    __shared__ uint4 Ash[ROUNDS * 2 * 32];   // 16 KB

    const int tid  = threadIdx.x;
    const int lane = tid & 31;
    const int warp = tid >> 5;
    const int ks   = blockIdx.y;
    const int cb   = blockIdx.x;
    const int colbase = cb * NTILE + warp * 32;
    const int i4 = lane & 3;   // threadID_in_group
    const int g8 = lane >> 2;  // groupID
    const int ck0 = ks * KC;

    const half2 c1032 = __half2half2(__ushort_as_half((unsigned short)0x6408)); // 1032.0

    // ---- stage x slice (fp32 -> fp16) into permuted A-fragment layout ----
    #pragma unroll
    for (int s = 0; s < KC / NTHREADS; ++s) {       // 4 tasks/thread
        int tau = tid + s * NTHREADS;
        int r   = tau >> 5;
        int rem = tau & 31;
        int g   = rem >> 2;
        int ii  = rem & 3;
        int b   = ck0 + r * 32 + ii * 8;
        const float* xlo = x + (size_t)g       * KK + b;
        const float* xhi = x + (size_t)(g + 8) * KK + b;
        float4 l0 = *reinterpret_cast<const float4*>(xlo);
        float4 l1 = *reinterpret_cast<const float4*>(xlo + 4);
        float4 h0 = *reinterpret_cast<const float4*>(xhi);
        float4 h1 = *reinterpret_cast<const float4*>(xhi + 4);
        uint4 e0, e1;
        e0.x = packh2(l0.x, l1.x);   // (b+0, b+4) row g     -> a0 of mma j=0
        e0.y = packh2(h0.x, h1.x);   //            row g+8   -> a1
        e0.z = packh2(l0.y, l1.y);   // (b+1, b+5)           -> a2
        e0.w = packh2(h0.y, h1.y);   //                      -> a3
        e1.x = packh2(l0.z, l1.z);   // (b+2, b+6)           -> mma j=1
        e1.y = packh2(h0.z, h1.z);
        e1.z = packh2(l0.w, l1.w);   // (b+3, b+7)
        e1.w = packh2(h0.w, h1.w);
        Ash[(r * 2 + 0) * 32 + rem] = e0;
        Ash[(r * 2 + 1) * 32 + rem] = e1;
    }
    __syncthreads();

    // qweight: packed rows [ks*64 .. ks*64+63]; lane reads row (4r+i4), cols colbase+4*g8..+3
    const int4* qp = reinterpret_cast<const int4*>(
        qweight + (size_t)(ks * 64 + i4) * NN + colbase) + g8;
    // scales: group rows [ks*4 .. ks*4+3]; lane reads cols colbase+4*g8..+3
    const float4* scp = reinterpret_cast<const float4*>(
        scales + (size_t)(ks * 4) * NN + colbase) + g8;

    float accm[4][4] = {};
    uint4 wqbuf[2];            // rolling depth-2 round prefetch
    half2 hs[2][4];

    wqbuf[0] = *reinterpret_cast<const uint4*>(qp);                 // round 0
    wqbuf[1] = *reinterpret_cast<const uint4*>(qp + R4STRIDE);      // round 1
    {
        float4 sf = __ldg(scp);
        hs[0][0] = __half2half2(__float2half_rn(sf.x));
        hs[0][1] = __half2half2(__float2half_rn(sf.y));
        hs[0][2] = __half2half2(__float2half_rn(sf.z));
        hs[0][3] = __half2half2(__float2half_rn(sf.w));
    }

    #pragma unroll
    for (int r4 = 0; r4 < 4; ++r4) {               // 4 scale-groups of 128 k
        const int cur = r4 & 1, nxt = cur ^ 1;
        if (r4 < 3) {                              // prefetch next group's scales
            float4 sf = __ldg(scp + (size_t)(r4 + 1) * SCSTRIDE);
            hs[nxt][0] = __half2half2(__float2half_rn(sf.x));
            hs[nxt][1] = __half2half2(__float2half_rn(sf.y));
            hs[nxt][2] = __half2half2(__float2half_rn(sf.z));
            hs[nxt][3] = __half2half2(__float2half_rn(sf.w));
        }
        #pragma unroll
        for (int rr = 0; rr < 4; ++rr) {           // 4 rounds = 128 k
            int r = r4 * 4 + rr;
            uint4 w = wqbuf[r & 1];
            if (r + 2 < ROUNDS)                    // rolling prefetch, distance 2
                wqbuf[r & 1] = *reinterpret_cast<const uint4*>(qp + (size_t)(r + 2) * R4STRIDE);
            uint4 va = Ash[(r * 2 + 0) * 32 + lane];
            uint4 vb = Ash[(r * 2 + 1) * 32 + lane];
            procj(accm[0], w.x, hs[cur][0], va, vb, c1032);
            procj(accm[1], w.y, hs[cur][1], va, vb, c1032);
            procj(accm[2], w.z, hs[cur][2], va, vb, c1032);
            procj(accm[3], w.w, hs[cur][3], va, vb, c1032);
        }
    }

    // ---- write fp32 partials: group j's C col = colbase + 8*i4 + j (+4 for c[1]/c[3]).
    // Across j=0..3 these are 4 consecutive columns -> float4 stores.
    {
        float* spt = g_scratch + (size_t)ks * (MM * NN);
        size_t base = (size_t)g8 * NN + colbase + 8 * i4;
        *reinterpret_cast<float4*>(spt + base) =
            make_float4(accm[0][0], accm[1][0], accm[2][0], accm[3][0]);
        *reinterpret_cast<float4*>(spt + base + 4) =
            make_float4(accm[0][1], accm[1][1], accm[2][1], accm[3][1]);
        *reinterpret_cast<float4*>(spt + base + (size_t)8 * NN) =
            make_float4(accm[0][2], accm[1][2], accm[2][2], accm[3][2]);
        *reinterpret_cast<float4*>(spt + base + (size_t)8 * NN + 4) =
            make_float4(accm[0][3], accm[1][3], accm[2][3], accm[3][3]);
    }
}

// 1 float per thread: 131072 threads -> ~28 warps/SM, 2x the latency cover of R7.
__global__ void qlinear_reduce(const float* __restrict__ bias, float* __restrict__ out) {
    int idx = blockIdx.x * blockDim.x + threadIdx.x;     // float index over M*N
    if (idx >= MM * NN) return;
    int n = idx & (NN - 1);
    float a = 0.f;
    #pragma unroll
    for (int s = 0; s < SPLITK; ++s)                     // fixed order: deterministic
        a += g_scratch[(size_t)s * MM * NN + idx];
    // replicate reference: fp16(dot) + fp16 bias, fp16 add, widen to f32
    out[idx] = __half2float(__hadd(__float2half_rn(a), __float2half_rn(__ldg(bias + n))));
}

// diagnostic no-ops: shift ncu's launch index 5 onto the GEMM (pattern d,g,r,d -> 5 mod 4 = 1)
__global__ void noop_kernel() {}

extern "C" void kernel_launch(void* const* d_in, const int* in_sizes, int n_in,
                              void* d_out, int out_size) {
    // identify inputs by unique element counts (robust to ordering)
    const float* x = nullptr; const int* qw = nullptr;
    const float* sc = nullptr; const float* bias = nullptr;
    for (int i = 0; i < n_in; ++i) {
        switch (in_sizes[i]) {
            case MM * KK:              x    = (const float*)d_in[i]; break;  // 131072
            case (KK / 8) * NN:        qw   = (const int*)  d_in[i]; break;  // 8388608
            case (KK / GROUPK) * NN:   sc   = (const float*)d_in[i]; break;  // 524288
            case NN:                   bias = (const float*)d_in[i]; break;  // 8192
        }
    }
    float* out = (float*)d_out;

    noop_kernel<<<1, 1>>>();

    dim3 grid(NCB, SPLITK);   // 64 x 16 = 1024 blocks, one full wave at 7/SM
    qlinear_gemm<<<grid, NTHREADS>>>(x, qw, sc);

    int tot = MM * NN;        // 131072 threads
    qlinear_reduce<<<(tot + 255) / 256, 256>>>(bias, out);

    noop_kernel<<<1, 1>>>();
}

// round 9
// speedup vs baseline: 1.1366x; 1.1366x over previous
#include <cuda_runtime.h>
#include <cuda_fp16.h>
#include <cstdint>

#define MM 16
#define KK 8192
#define NN 8192
#define GROUPK 128
#define SPLITK 16
#define KC     512             // k per block (= KPER)
#define NTILE  128             // columns per block (4 warps x 32 cols)
#define WARPS  4
#define NTHREADS (WARPS * 32)
#define NCB    (NN / NTILE)    // 64 column-blocks
#define ROUNDS (KC / 32)       // 16 rounds of 32-k
#define R4STRIDE  (NN)         // int4 units between rounds (4 rows * NN ints / 4)
#define SCSTRIDE  (NN / 4)     // float4 units per scale-group row

// fp16 partial sums, one slab per K-split (each element written exactly once)
__device__ __half g_scratch_h[SPLITK * MM * NN];    // 4 MB
// x pre-converted to fp16 in A-fragment order: [ks*16+r][j][lane] uint4
__device__ uint4 g_xfrag[256 * 2 * 32];             // 256 KB

// (v & 0x000F000F) | 0x64006400 -> half2 (1024+nib_lo, 1024+nib_hi); -1032 exactly -> (nib-8)
__device__ __forceinline__ uint32_t dq4(uint32_t v, half2 c1032) {
    uint32_t h;
    asm("lop3.b32 %0, %1, %2, %3, 0xEA;"
        : "=r"(h) : "r"(v), "r"(0x000F000Fu), "r"(0x64006400u));
    half2 hh = __hsub2(*reinterpret_cast<half2*>(&h), c1032);
    return *reinterpret_cast<uint32_t*>(&hh);
}

__device__ __forceinline__ uint32_t mulsc(uint32_t w, half2 s) {
    half2 r = __hmul2(*reinterpret_cast<half2*>(&w), s);   // fp16 RN: matches reference w
    return *reinterpret_cast<uint32_t*>(&r);
}

__device__ __forceinline__ uint32_t packh2(float a, float b) {
    half2 h = __floats2half2_rn(a, b);
    return *reinterpret_cast<uint32_t*>(&h);
}

__device__ __forceinline__ void mma16816(float* c,
                                         uint32_t a0, uint32_t a1, uint32_t a2, uint32_t a3,
                                         uint32_t b0, uint32_t b1) {
    asm volatile(
        "mma.sync.aligned.m16n8k16.row.col.f32.f16.f16.f32 "
        "{%0,%1,%2,%3}, {%4,%5,%6,%7}, {%8,%9}, {%0,%1,%2,%3};\n"
        : "+f"(c[0]), "+f"(c[1]), "+f"(c[2]), "+f"(c[3])
        : "r"(a0), "r"(a1), "r"(a2), "r"(a3), "r"(b0), "r"(b1));
}

__device__ __forceinline__ void procj(float* acc, uint32_t wj, half2 s,
                                      const uint4& va, const uint4& vb, half2 c1032) {
    uint32_t b00 = mulsc(dq4(wj,       c1032), s);
    uint32_t b01 = mulsc(dq4(wj >> 4,  c1032), s);
    uint32_t b02 = mulsc(dq4(wj >> 8,  c1032), s);
    uint32_t b03 = mulsc(dq4(wj >> 12, c1032), s);
    mma16816(acc, va.x, va.y, va.z, va.w, b00, b01);
    mma16816(acc, vb.x, vb.y, vb.z, vb.w, b02, b03);
}

// Convert x (fp32) into fp16 A-fragment order, once per launch.
// Task t = (global round rg 0..255, slot rem 0..31); writes e0 (mma j=0) and e1 (j=1).
__global__ void prep_x(const float* __restrict__ x) {
    int t = blockIdx.x * blockDim.x + threadIdx.x;    // 0..8191
    int rem = t & 31;
    int rg  = t >> 5;                                 // ks*16 + r
    int g   = rem >> 2;
    int ii  = rem & 3;
    int b   = rg * 32 + ii * 8;
    const float* xlo = x + (size_t)g       * KK + b;
    const float* xhi = x + (size_t)(g + 8) * KK + b;
    float4 l0 = *reinterpret_cast<const float4*>(xlo);
    float4 l1 = *reinterpret_cast<const float4*>(xlo + 4);
    float4 h0 = *reinterpret_cast<const float4*>(xhi);
    float4 h1 = *reinterpret_cast<const float4*>(xhi + 4);
    uint4 e0, e1;
    e0.x = packh2(l0.x, l1.x);   // (b+0, b+4) row g     -> a0 of mma j=0
    e0.y = packh2(h0.x, h1.x);   //            row g+8   -> a1
    e0.z = packh2(l0.y, l1.y);   // (b+1, b+5)           -> a2
    e0.w = packh2(h0.y, h1.y);   //                      -> a3
    e1.x = packh2(l0.z, l1.z);   // (b+2, b+6)           -> mma j=1
    e1.y = packh2(h0.z, h1.z);
    e1.z = packh2(l0.w, l1.w);   // (b+3, b+7)
    e1.w = packh2(h0.w, h1.w);
    g_xfrag[rg * 64 + rem]      = e0;
    g_xfrag[rg * 64 + 32 + rem] = e1;
}

// Smem-free GEMM. One int32 of qweight (col c, packed row pr) feeds 4 B-regs of
// col c; lane (g8,i4) loads int4 = cols colbase+4*g8+{0..3} of packed row 4r+i4
// (coalesced 128B). MMA group j uses col set {colbase+4n+j}; undone in epilogue
// indexing. A fragments stream from g_xfrag (L1/L2-resident), rolling prefetch d=2.
__global__ void __launch_bounds__(NTHREADS, 7)
qlinear_gemm(const int* __restrict__ qweight, const float* __restrict__ scales)
{
    const int tid  = threadIdx.x;
    const int lane = tid & 31;
    const int warp = tid >> 5;
    const int ks   = blockIdx.y;
    const int cb   = blockIdx.x;
    const int colbase = cb * NTILE + warp * 32;
    const int i4 = lane & 3;   // threadID_in_group
    const int g8 = lane >> 2;  // groupID

    const half2 c1032 = __half2half2(__ushort_as_half((unsigned short)0x6408)); // 1032.0

    // qweight: packed rows [ks*64 .. ks*64+63]; lane reads row (4r+i4), cols colbase+4*g8..+3
    const int4* qp = reinterpret_cast<const int4*>(
        qweight + (size_t)(ks * 64 + i4) * NN + colbase) + g8;
    // scales: group rows [ks*4 .. ks*4+3]; lane reads cols colbase+4*g8..+3
    const float4* scp = reinterpret_cast<const float4*>(
        scales + (size_t)(ks * 4) * NN + colbase) + g8;
    // A fragments for this ks
    const uint4* xf = g_xfrag + (size_t)(ks * ROUNDS) * 64 + lane;

    float accm[4][4] = {};
    uint4 wqbuf[2], vaf[2], vbf[2];    // rolling depth-2 round prefetch

    wqbuf[0] = *reinterpret_cast<const uint4*>(qp);
    wqbuf[1] = *reinterpret_cast<const uint4*>(qp + R4STRIDE);
    vaf[0] = xf[0];       vbf[0] = xf[32];
    vaf[1] = xf[64];      vbf[1] = xf[96];

    #pragma unroll
    for (int r4 = 0; r4 < 4; ++r4) {               // 4 scale-groups of 128 k
        half2 hs[4];
        {
            float4 sf = __ldg(scp + (size_t)r4 * SCSTRIDE);
            hs[0] = __half2half2(__float2half_rn(sf.x));
            hs[1] = __half2half2(__float2half_rn(sf.y));
            hs[2] = __half2half2(__float2half_rn(sf.z));
            hs[3] = __half2half2(__float2half_rn(sf.w));
        }
        #pragma unroll
        for (int rr = 0; rr < 4; ++rr) {           // 4 rounds = 128 k
            int r = r4 * 4 + rr;
            uint4 w  = wqbuf[r & 1];
            uint4 va = vaf[r & 1];
            uint4 vb = vbf[r & 1];
            if (r + 2 < ROUNDS) {                  // rolling prefetch, distance 2
                wqbuf[r & 1] = *reinterpret_cast<const uint4*>(qp + (size_t)(r + 2) * R4STRIDE);
                vaf[r & 1]   = xf[(r + 2) * 64];
                vbf[r & 1]   = xf[(r + 2) * 64 + 32];
            }
            procj(accm[0], w.x, hs[0], va, vb, c1032);
            procj(accm[1], w.y, hs[1], va, vb, c1032);
            procj(accm[2], w.z, hs[2], va, vb, c1032);
            procj(accm[3], w.w, hs[3], va, vb, c1032);
        }
    }

    // ---- write fp16 partials: group j's C col = colbase + 8*i4 + j (+4 for c[1]/c[3]).
    // 8 consecutive cols per row -> one 16B store per row.
    {
        __half* spt = g_scratch_h + (size_t)ks * (MM * NN);
        size_t base = (size_t)g8 * NN + colbase + 8 * i4;
        uint4 s0, s1;
        s0.x = packh2(accm[0][0], accm[1][0]); s0.y = packh2(accm[2][0], accm[3][0]);
        s0.z = packh2(accm[0][1], accm[1][1]); s0.w = packh2(accm[2][1], accm[3][1]);
        s1.x = packh2(accm[0][2], accm[1][2]); s1.y = packh2(accm[2][2], accm[3][2]);
        s1.z = packh2(accm[0][3], accm[1][3]); s1.w = packh2(accm[2][3], accm[3][3]);
        *reinterpret_cast<uint4*>(spt + base)                   = s0;
        *reinterpret_cast<uint4*>(spt + base + (size_t)8 * NN)  = s1;
    }
}

// half2 per thread over M*N/2 positions, 16 slabs, fp32 accumulate.
__global__ void qlinear_reduce(const float* __restrict__ bias, float* __restrict__ out) {
    int idx2 = blockIdx.x * blockDim.x + threadIdx.x;    // half2 index over M*N/2
    if (idx2 >= MM * NN / 2) return;
    int n2 = idx2 & (NN / 2 - 1);
    const half2* sp = reinterpret_cast<const half2*>(g_scratch_h) + idx2;
    float a = 0.f, b = 0.f;
    #pragma unroll
    for (int s = 0; s < SPLITK; ++s) {                   // fixed order: deterministic
        half2 p = sp[(size_t)s * (MM * NN / 2)];
        a += __low2float(p); b += __high2float(p);
    }
    const float2 bv = *reinterpret_cast<const float2*>(bias + n2 * 2);
    // replicate reference: fp16(dot) + fp16 bias, fp16 add, widen to f32
    float2 o;
    o.x = __half2float(__hadd(__float2half_rn(a), __float2half_rn(bv.x)));
    o.y = __half2float(__hadd(__float2half_rn(b), __float2half_rn(bv.y)));
    *reinterpret_cast<float2*>(out + (size_t)idx2 * 2) = o;
}

extern "C" void kernel_launch(void* const* d_in, const int* in_sizes, int n_in,
                              void* d_out, int out_size) {
    // identify inputs by unique element counts (robust to ordering)
    const float* x = nullptr; const int* qw = nullptr;
    const float* sc = nullptr; const float* bias = nullptr;
    for (int i = 0; i < n_in; ++i) {
        switch (in_sizes[i]) {
            case MM * KK:              x    = (const float*)d_in[i]; break;  // 131072
            case (KK / 8) * NN:        qw   = (const int*)  d_in[i]; break;  // 8388608
            case (KK / GROUPK) * NN:   sc   = (const float*)d_in[i]; break;  // 524288
            case NN:                   bias = (const float*)d_in[i]; break;  // 8192
        }
    }
    float* out = (float*)d_out;

    prep_x<<<64, 128>>>(x);                    // 8192 tasks

    dim3 grid(NCB, SPLITK);                    // 64 x 16 = 1024 blocks, 7/SM wave
    qlinear_gemm<<<grid, NTHREADS>>>(qw, sc);

    int tot2 = MM * NN / 2;                    // 65536 threads
    qlinear_reduce<<<(tot2 + 255) / 256, 256>>>(bias, out);
}

// round 10
// speedup vs baseline: 1.2909x; 1.1358x over previous
#include <cuda_runtime.h>
#include <cuda_fp16.h>
#include <cstdint>

#define MM 16
#define KK 8192
#define NN 8192
#define GROUPK 128
#define SPLITK 16
#define KC     512             // k per block (= KPER)
#define NTILE  128             // columns per block (4 warps x 32 cols)
#define WARPS  4
#define NTHREADS (WARPS * 32)
#define NCB    (NN / NTILE)    // 64 column-blocks
#define ROUNDS (KC / 32)       // 16 rounds of 32-k
#define R4STRIDE  (NN)         // int4 units between rounds (4 rows * NN ints / 4)
#define SCSTRIDE  (NN / 4)     // float4 units per scale-group row

// x pre-converted to fp16 in A-fragment order: [ks*16+r][j][lane] uint4
__device__ uint4 g_xfrag[256 * 2 * 32];             // 256 KB

// (v & 0x000F000F) | 0x64006400 -> half2 (1024+nib_lo, 1024+nib_hi); -1032 exactly -> (nib-8)
__device__ __forceinline__ uint32_t dq4(uint32_t v, half2 c1032) {
    uint32_t h;
    asm("lop3.b32 %0, %1, %2, %3, 0xEA;"
        : "=r"(h) : "r"(v), "r"(0x000F000Fu), "r"(0x64006400u));
    half2 hh = __hsub2(*reinterpret_cast<half2*>(&h), c1032);
    return *reinterpret_cast<uint32_t*>(&hh);
}

__device__ __forceinline__ uint32_t mulsc(uint32_t w, half2 s) {
    half2 r = __hmul2(*reinterpret_cast<half2*>(&w), s);   // fp16 RN: matches reference w
    return *reinterpret_cast<uint32_t*>(&r);
}

__device__ __forceinline__ uint32_t packh2(float a, float b) {
    half2 h = __floats2half2_rn(a, b);
    return *reinterpret_cast<uint32_t*>(&h);
}

__device__ __forceinline__ void mma16816(float* c,
                                         uint32_t a0, uint32_t a1, uint32_t a2, uint32_t a3,
                                         uint32_t b0, uint32_t b1) {
    asm volatile(
        "mma.sync.aligned.m16n8k16.row.col.f32.f16.f16.f32 "
        "{%0,%1,%2,%3}, {%4,%5,%6,%7}, {%8,%9}, {%0,%1,%2,%3};\n"
        : "+f"(c[0]), "+f"(c[1]), "+f"(c[2]), "+f"(c[3])
        : "r"(a0), "r"(a1), "r"(a2), "r"(a3), "r"(b0), "r"(b1));
}

__device__ __forceinline__ void procj(float* acc, uint32_t wj, half2 s,
                                      const uint4& va, const uint4& vb, half2 c1032) {
    uint32_t b00 = mulsc(dq4(wj,       c1032), s);
    uint32_t b01 = mulsc(dq4(wj >> 4,  c1032), s);
    uint32_t b02 = mulsc(dq4(wj >> 8,  c1032), s);
    uint32_t b03 = mulsc(dq4(wj >> 12, c1032), s);
    mma16816(acc, va.x, va.y, va.z, va.w, b00, b01);
    mma16816(acc, vb.x, vb.y, vb.z, vb.w, b02, b03);
}

// no-return vectorized f32 reduction into global (sm_90+)
__device__ __forceinline__ void redg_v4(float* p, float a, float b, float c, float d) {
    asm volatile("red.global.add.v4.f32 [%0], {%1, %2, %3, %4};"
                 :: "l"(p), "f"(a), "f"(b), "f"(c), "f"(d) : "memory");
}

// Combo front kernel: blocks 0-31 convert x into A-fragment order;
// blocks 32-95 initialize out with broadcast f32(f16(bias)) (clears poison).
__global__ void __launch_bounds__(256)
prep_combo(const float* __restrict__ x, const float* __restrict__ bias,
           float* __restrict__ out)
{
    int tid = threadIdx.x;
    if (blockIdx.x < 32) {
        int t = blockIdx.x * 256 + tid;               // 0..8191
        int rem = t & 31;
        int rg  = t >> 5;                             // ks*16 + r
        int g   = rem >> 2;
        int ii  = rem & 3;
        int b   = rg * 32 + ii * 8;
        const float* xlo = x + (size_t)g       * KK + b;
        const float* xhi = x + (size_t)(g + 8) * KK + b;
        float4 l0 = *reinterpret_cast<const float4*>(xlo);
        float4 l1 = *reinterpret_cast<const float4*>(xlo + 4);
        float4 h0 = *reinterpret_cast<const float4*>(xhi);
        float4 h1 = *reinterpret_cast<const float4*>(xhi + 4);
        uint4 e0, e1;
        e0.x = packh2(l0.x, l1.x);   // (b+0, b+4) row g     -> a0 of mma j=0
        e0.y = packh2(h0.x, h1.x);   //            row g+8   -> a1
        e0.z = packh2(l0.y, l1.y);   // (b+1, b+5)           -> a2
        e0.w = packh2(h0.y, h1.y);   //                      -> a3
        e1.x = packh2(l0.z, l1.z);   // (b+2, b+6)           -> mma j=1
        e1.y = packh2(h0.z, h1.z);
        e1.z = packh2(l0.w, l1.w);   // (b+3, b+7)
        e1.w = packh2(h0.w, h1.w);
        g_xfrag[rg * 64 + rem]      = e0;
        g_xfrag[rg * 64 + 32 + rem] = e1;
    } else {
        // init: 16384 threads x 2 float4 = 32768 float4 = all of out
        int i = (blockIdx.x - 32) * 256 + tid;        // 0..16383
        int n4 = i & (NN / 4 - 1);                    // same column set for both rows
        const float4 bv = *reinterpret_cast<const float4*>(bias + n4 * 4);
        float4 o;
        o.x = __half2float(__float2half_rn(bv.x));    // f32(f16(bias)) as in reference
        o.y = __half2float(__float2half_rn(bv.y));
        o.z = __half2float(__float2half_rn(bv.z));
        o.w = __half2float(__float2half_rn(bv.w));
        float4* out4 = reinterpret_cast<float4*>(out);
        out4[i]         = o;
        out4[i + 16384] = o;                          // +8 rows
    }
}

// Smem-free GEMM with atomic-reduce epilogue. One int32 of qweight (col c,
// packed row pr) feeds 4 B-regs of col c; lane (g8,i4) loads int4 = cols
// colbase+4*g8+{0..3} of packed row 4r+i4 (coalesced 128B). MMA group j uses
// col set {colbase+4n+j}; undone in epilogue indexing. A fragments stream from
// g_xfrag (L2-resident), rolling prefetch d=2. Partials land in out via
// red.global.add.v4.f32 (out pre-initialized with bias by prep_combo).
__global__ void __launch_bounds__(NTHREADS, 7)
qlinear_gemm(const int* __restrict__ qweight, const float* __restrict__ scales,
             float* __restrict__ out)
{
    const int tid  = threadIdx.x;
    const int lane = tid & 31;
    const int warp = tid >> 5;
    const int ks   = blockIdx.y;
    const int cb   = blockIdx.x;
    const int colbase = cb * NTILE + warp * 32;
    const int i4 = lane & 3;   // threadID_in_group
    const int g8 = lane >> 2;  // groupID

    const half2 c1032 = __half2half2(__ushort_as_half((unsigned short)0x6408)); // 1032.0

    // qweight: packed rows [ks*64 .. ks*64+63]; lane reads row (4r+i4), cols colbase+4*g8..+3
    const int4* qp = reinterpret_cast<const int4*>(
        qweight + (size_t)(ks * 64 + i4) * NN + colbase) + g8;
    // scales: group rows [ks*4 .. ks*4+3]; lane reads cols colbase+4*g8..+3
    const float4* scp = reinterpret_cast<const float4*>(
        scales + (size_t)(ks * 4) * NN + colbase) + g8;
    // A fragments for this ks
    const uint4* xf = g_xfrag + (size_t)(ks * ROUNDS) * 64 + lane;

    float accm[4][4] = {};
    uint4 wqbuf[2], vaf[2], vbf[2];    // rolling depth-2 round prefetch

    wqbuf[0] = *reinterpret_cast<const uint4*>(qp);
    wqbuf[1] = *reinterpret_cast<const uint4*>(qp + R4STRIDE);
    vaf[0] = xf[0];       vbf[0] = xf[32];
    vaf[1] = xf[64];      vbf[1] = xf[96];

    #pragma unroll
    for (int r4 = 0; r4 < 4; ++r4) {               // 4 scale-groups of 128 k
        half2 hs[4];
        {
            float4 sf = __ldg(scp + (size_t)r4 * SCSTRIDE);
            hs[0] = __half2half2(__float2half_rn(sf.x));
            hs[1] = __half2half2(__float2half_rn(sf.y));
            hs[2] = __half2half2(__float2half_rn(sf.z));
            hs[3] = __half2half2(__float2half_rn(sf.w));
        }
        #pragma unroll
        for (int rr = 0; rr < 4; ++rr) {           // 4 rounds = 128 k
            int r = r4 * 4 + rr;
            uint4 w  = wqbuf[r & 1];
            uint4 va = vaf[r & 1];
            uint4 vb = vbf[r & 1];
            if (r + 2 < ROUNDS) {                  // rolling prefetch, distance 2
                wqbuf[r & 1] = *reinterpret_cast<const uint4*>(qp + (size_t)(r + 2) * R4STRIDE);
                vaf[r & 1]   = xf[(r + 2) * 64];
                vbf[r & 1]   = xf[(r + 2) * 64 + 32];
            }
            procj(accm[0], w.x, hs[0], va, vb, c1032);
            procj(accm[1], w.y, hs[1], va, vb, c1032);
            procj(accm[2], w.z, hs[2], va, vb, c1032);
            procj(accm[3], w.w, hs[3], va, vb, c1032);
        }
    }

    // ---- atomic-reduce fp32 partials into out (bias pre-added by init).
    // group j's C col = colbase + 8*i4 + j (rows g8, g8+8); +4 for c[1]/c[3].
    {
        float* op = out + (size_t)g8 * NN + colbase + 8 * i4;
        redg_v4(op,     accm[0][0], accm[1][0], accm[2][0], accm[3][0]);
        redg_v4(op + 4, accm[0][1], accm[1][1], accm[2][1], accm[3][1]);
        float* op2 = op + (size_t)8 * NN;
        redg_v4(op2,     accm[0][2], accm[1][2], accm[2][2], accm[3][2]);
        redg_v4(op2 + 4, accm[0][3], accm[1][3], accm[2][3], accm[3][3]);
    }
}

extern "C" void kernel_launch(void* const* d_in, const int* in_sizes, int n_in,
                              void* d_out, int out_size) {
    // identify inputs by unique element counts (robust to ordering)
    const float* x = nullptr; const int* qw = nullptr;
    const float* sc = nullptr; const float* bias = nullptr;
    for (int i = 0; i < n_in; ++i) {
        switch (in_sizes[i]) {
            case MM * KK:              x    = (const float*)d_in[i]; break;  // 131072
            case (KK / 8) * NN:        qw   = (const int*)  d_in[i]; break;  // 8388608
            case (KK / GROUPK) * NN:   sc   = (const float*)d_in[i]; break;  // 524288
            case NN:                   bias = (const float*)d_in[i]; break;  // 8192
        }
    }
    float* out = (float*)d_out;

    prep_combo<<<96, 256>>>(x, bias, out);     // x-permute + out-init (bias)

    dim3 grid(NCB, SPLITK);                    // 64 x 16 = 1024 blocks, 7/SM wave
    qlinear_gemm<<<grid, NTHREADS>>>(qw, sc, out);
}